// round 3
// baseline (speedup 1.0000x reference)
#include <cuda_runtime.h>
#include <math.h>

#define T_STEPS 256
#define B_SZ    256
#define I_SZ    128
#define N_SZ    1024
#define O_SZ    64
#define M_ROWS  512   // stacked [x; y]

#define GRID_MAIN 128
#define BM 128
#define BN 32
#define BK 32
#define WSTR 1036     // 1024 + 12 pad -> conflict-free B-frag LDS
#define ASTR 36       // 32 + 4 pad   -> conflict-free A-frag LDS
#define LSTR 33       // local state arrays

#define SMEM_FLOATS (32*WSTR + 2*128*ASTR + 3*128*LSTR + 64)
#define SMEM_BYTES  (SMEM_FLOATS * 4)

__device__ float g_X [M_ROWS * N_SZ];
__device__ float g_S0[M_ROWS * N_SZ];
__device__ float g_S1[M_ROWS * N_SZ];
__device__ float g_F0[B_SZ * N_SZ];
__device__ float g_fc[N_SZ];
__device__ unsigned g_bar_count = 0;
__device__ unsigned g_bar_phase = 0;

__constant__ float C_H     = 0.05f;
__constant__ float C_OMEGA = 6.283185307179586f;
__constant__ float C_GAMMA = 0.1f;
__constant__ float C_LAM   = 1.0f;
__constant__ float C_GAIN  = 0.03125f;  // 1/sqrt(1024)

// ---------------------------------------------------------------------------
__global__ void init_kernel(const float* __restrict__ b_ih) {
    int idx = blockIdx.x * blockDim.x + threadIdx.x;
    int stride = gridDim.x * blockDim.x;
    for (int i = idx; i < M_ROWS * N_SZ; i += stride) g_S0[i] = 0.0f;
    if (idx < N_SZ) g_fc[idx] = tanhf(b_ih[idx]);
}

// ---------------------------------------------------------------------------
__global__ void forcing_kernel(const float* __restrict__ batch,
                               const float* __restrict__ W_ih,
                               const float* __restrict__ b_ih) {
    int idx = blockIdx.x * blockDim.x + threadIdx.x;
    int b = idx >> 10;
    int n = idx & (N_SZ - 1);
    const float4* xp = (const float4*)(batch + b * I_SZ);
    const float4* wp = (const float4*)(W_ih + n * I_SZ);
    float s = 0.0f;
#pragma unroll 8
    for (int i = 0; i < I_SZ / 4; ++i) {
        float4 x = __ldg(xp + i);
        float4 w = __ldg(wp + i);
        s += x.x * w.x + x.y * w.y + x.z * w.z + x.w * w.w;
    }
    g_F0[idx] = tanhf(s + __ldg(b_ih + n));
}

// ---------------------------------------------------------------------------
// grid barrier, cooperative-groups style: ONE gpu-scope fence in tid0 only.
// Cumulativity: all CTA writes happen-before the syncthreads, which
// happens-before tid0's fence -> release via the atomic chain.
// ---------------------------------------------------------------------------
__device__ __forceinline__ void grid_barrier(unsigned G) {
    __syncthreads();
    if (threadIdx.x == 0) {
        __threadfence();                   // release (publishes whole CTA's writes)
        unsigned p = *(volatile unsigned*)&g_bar_phase;
        unsigned a = atomicAdd(&g_bar_count, 1u);
        if (a == G - 1u) {
            atomicExch(&g_bar_count, 0u);
            __threadfence();
            atomicAdd(&g_bar_phase, 1u);   // release
        } else {
            while (*(volatile unsigned*)&g_bar_phase == p) { }
        }
        __threadfence();                   // acquire
    }
    __syncthreads();
}

// ---------------------------------------------------------------------------
__device__ __forceinline__ float f2tf32(float x) {
    float r;
    asm("cvt.rna.tf32.f32 %0, %1;" : "=f"(r) : "f"(x));
    return r;
}

__device__ __forceinline__ void mma_tf32(float* d, const float* a, const float* b) {
    const unsigned* A = (const unsigned*)a;
    const unsigned* B = (const unsigned*)b;
    asm volatile(
        "mma.sync.aligned.m16n8k8.row.col.f32.tf32.tf32.f32 "
        "{%0,%1,%2,%3},{%4,%5,%6,%7},{%8,%9},{%0,%1,%2,%3};"
        : "+f"(d[0]), "+f"(d[1]), "+f"(d[2]), "+f"(d[3])
        : "r"(A[0]), "r"(A[1]), "r"(A[2]), "r"(A[3]), "r"(B[0]), "r"(B[1]));
}

// ---------------------------------------------------------------------------
// main persistent kernel.
// Grid 128 = 4 m-tiles (64 batches, x+y => 128 A-rows) x 32 n-tiles (32 cols).
// W n-slice resident in SMEM (tf32). A: depth-2 register prefetch, raw fp32
// into SMEM (mma.sync truncates to tf32 in HW). Epilogue fully SMEM-local.
// ---------------------------------------------------------------------------
__global__ void __launch_bounds__(256, 1)
main_kernel(const float* __restrict__ W_hh, const float* __restrict__ b_hh) {
    extern __shared__ float sm[];
    float* Wsm  = sm;
    float* Asm  = Wsm + 32 * WSTR;
    float* Sloc = Asm + 2 * 128 * ASTR;
    float* Xs   = Sloc + 128 * LSTR;
    float* Ks   = Xs + 128 * LSTR;
    float* fcs  = Ks + 128 * LSTR;
    float* bhs  = fcs + 32;

    const int tid  = threadIdx.x;
    const int lane = tid & 31;
    const int wm   = tid >> 5;           // warp 0..7 -> 16-row strip
    const int bn   = blockIdx.x & 31;
    const int bm   = blockIdx.x >> 5;
    const int N0   = bn * BN;
    const int batch0 = bm * 64;
    const unsigned G = gridDim.x;
    const bool isx = (wm < 4);

    // ---- one-time init ----
    for (int i = tid; i < 32 * 256; i += 256) {
        int r = i >> 8, c4 = (i & 255) * 4;
        float4 w = __ldg((const float4*)(W_hh + (N0 + r) * N_SZ + c4));
        float* p = &Wsm[r * WSTR + c4];
        p[0] = f2tf32(w.x); p[1] = f2tf32(w.y); p[2] = f2tf32(w.z); p[3] = f2tf32(w.w);
    }
    for (int i = tid; i < 128 * LSTR; i += 256) { Sloc[i] = 0.0f; Xs[i] = 0.0f; Ks[i] = 0.0f; }
    if (tid < 32) { fcs[tid] = g_fc[N0 + tid]; bhs[tid] = __ldg(b_hh + N0 + tid); }
    __syncthreads();

    // ---- A loader mapping: 4 float4 per thread per chunk ----
    int arow[4], gofs[4];
    const int c4 = (tid & 7) * 4;
#pragma unroll
    for (int i = 0; i < 4; ++i) {
        arow[i] = i * 32 + (tid >> 3);
        int grow = batch0 + arow[i] + (arow[i] >= 64 ? 192 : 0);
        gofs[i] = grow * N_SZ + c4;
    }

    float* const bufs[2] = { g_S0, g_S1 };

    for (int t = 0; t < T_STEPS; ++t) {
        for (int s = 0; s < 4; ++s) {
            const float* Sin  = bufs[s & 1];
            float*       Sout = bufs[(s + 1) & 1];

            float acc[4][4];
#pragma unroll
            for (int i = 0; i < 4; ++i)
#pragma unroll
                for (int j = 0; j < 4; ++j) acc[i][j] = 0.0f;

            float4 cur[4], nxt[4];
#pragma unroll
            for (int i = 0; i < 4; ++i) cur[i] = __ldcg((const float4*)(Sin + gofs[i]));
#pragma unroll
            for (int i = 0; i < 4; ++i) nxt[i] = __ldcg((const float4*)(Sin + gofs[i] + BK));

            for (int it = 0; it < N_SZ / BK; ++it) {
                float* Ab = Asm + (it & 1) * 128 * ASTR;
#pragma unroll
                for (int i = 0; i < 4; ++i)
                    *(float4*)&Ab[arow[i] * ASTR + c4] = cur[i];
                __syncthreads();

#pragma unroll
                for (int i = 0; i < 4; ++i) cur[i] = nxt[i];
                if (it + 2 < N_SZ / BK) {
                    const int k0 = (it + 2) * BK;
#pragma unroll
                    for (int i = 0; i < 4; ++i)
                        nxt[i] = __ldcg((const float4*)(Sin + gofs[i] + k0));
                }

                const int kb = it * BK;
#pragma unroll
                for (int kk = 0; kk < BK; kk += 8) {
                    float af[4];
                    const int rA = wm * 16 + (lane >> 2);
                    const int cA = kk + (lane & 3);
                    af[0] = Ab[rA * ASTR + cA];
                    af[1] = Ab[(rA + 8) * ASTR + cA];
                    af[2] = Ab[rA * ASTR + cA + 4];
                    af[3] = Ab[(rA + 8) * ASTR + cA + 4];
#pragma unroll
                    for (int nt = 0; nt < 4; ++nt) {
                        const int rB = nt * 8 + (lane >> 2);
                        const int cB = kb + kk + (lane & 3);
                        float bf[2];
                        bf[0] = Wsm[rB * WSTR + cB];
                        bf[1] = Wsm[rB * WSTR + cB + 4];
                        mma_tf32(acc[nt], af, bf);
                    }
                }
            }

            // ---------------- fused RK4-stage epilogue (all local) ----------------
            const float cmul = (s == 2) ? C_H : 0.5f * C_H;
            const int r0 = wm * 16 + (lane >> 2);
            float kv[4][4];
#pragma unroll
            for (int nt = 0; nt < 4; ++nt) {
#pragma unroll
                for (int e = 0; e < 4; ++e) {
                    const int rl = r0 + 8 * (e >> 1);
                    const int cl = nt * 8 + 2 * (lane & 3) + (e & 1);
                    const int rx = isx ? rl : rl - 64;
                    const float sx = Sloc[rx * LSTR + cl];
                    const float sy = Sloc[(rx + 64) * LSTR + cl];
                    const float amp = C_LAM - (sx * sx + sy * sy);
                    const float rr = acc[nt][e];
                    float k;
                    if (isx) {
                        float F = (t == 0) ? g_F0[(batch0 + rx) * N_SZ + N0 + cl] : fcs[cl];
                        k = amp * sx - C_OMEGA * sy + C_GAIN * (rr + bhs[cl]) + F - C_GAMMA * sx;
                    } else {
                        k = amp * sy + C_OMEGA * sx + C_GAIN * (rr + bhs[cl]) - C_GAMMA * sy;
                    }
                    kv[nt][e] = k;
                }
            }
            __syncthreads();  // all Sloc reads done before overwrites
#pragma unroll
            for (int nt = 0; nt < 4; ++nt) {
#pragma unroll
                for (int eh = 0; eh < 2; ++eh) {
                    const int rl  = r0 + 8 * eh;
                    const int cl0 = nt * 8 + 2 * (lane & 3);
                    float2 so;
#pragma unroll
                    for (int j = 0; j < 2; ++j) {
                        const int il = rl * LSTR + cl0 + j;
                        const float k = kv[nt][eh * 2 + j];
                        const float xv = Xs[il];
                        float sv;
                        if (s == 0)      { Ks[il] = k;                    sv = xv + cmul * k; }
                        else if (s == 3) { float xn = xv + (C_H / 6.0f) * (Ks[il] + k);
                                           Xs[il] = xn;                   sv = xn; }
                        else             { Ks[il] += 2.0f * k;            sv = xv + cmul * k; }
                        (j == 0 ? so.x : so.y) = sv;
                        Sloc[il] = sv;
                    }
                    const int grow = batch0 + rl + (isx ? 0 : 192);
                    const int gi = grow * N_SZ + N0 + cl0;
                    *(float2*)(Sout + gi) = so;
                    if (t == T_STEPS - 1 && s == 3) *(float2*)(g_X + gi) = so;
                }
            }
            grid_barrier(G);
        }
    }
}

// ---------------------------------------------------------------------------
__global__ void out_kernel(const float* __restrict__ W_ho,
                           const float* __restrict__ b_ho,
                           float* __restrict__ out) {
    int b   = blockIdx.x;
    int tid = threadIdx.x;
    int o   = tid >> 2;
    int q   = tid & 3;
    const float4* xp = (const float4*)(g_X + b * N_SZ + q * 256);
    const float4* wp = (const float4*)(W_ho + o * N_SZ + q * 256);
    float s = 0.0f;
#pragma unroll 8
    for (int i = 0; i < 64; ++i) {
        float4 x = xp[i];
        float4 w = __ldg(wp + i);
        s += x.x * w.x + x.y * w.y + x.z * w.z + x.w * w.w;
    }
    s += __shfl_xor_sync(0xffffffffu, s, 1);
    s += __shfl_xor_sync(0xffffffffu, s, 2);
    if (q == 0) out[b * O_SZ + o] = s + __ldg(b_ho + o);
}

// ---------------------------------------------------------------------------
extern "C" void kernel_launch(void* const* d_in, const int* in_sizes, int n_in,
                              void* d_out, int out_size) {
    const float* batch = (const float*)d_in[0];
    const float* W_ih  = (const float*)d_in[1];
    const float* b_ih  = (const float*)d_in[2];
    const float* W_hh  = (const float*)d_in[3];
    const float* b_hh  = (const float*)d_in[4];
    const float* W_ho  = (const float*)d_in[5];
    const float* b_ho  = (const float*)d_in[6];
    float* out = (float*)d_out;

    cudaFuncSetAttribute(main_kernel,
                         cudaFuncAttributeMaxDynamicSharedMemorySize, SMEM_BYTES);

    init_kernel<<<512, 256>>>(b_ih);
    forcing_kernel<<<(B_SZ * N_SZ) / 256, 256>>>(batch, W_ih, b_ih);
    main_kernel<<<GRID_MAIN, 256, SMEM_BYTES>>>(W_hh, b_hh);
    out_kernel<<<B_SZ, 256>>>(W_ho, b_ho, out);
}

// round 5
// speedup vs baseline: 1.9363x; 1.9363x over previous
#include <cuda_runtime.h>
#include <cuda_fp16.h>
#include <math.h>
#include <stdint.h>

#define T_STEPS 256
#define B_SZ    256
#define I_SZ    128
#define N_SZ    1024
#define O_SZ    64
#define M_ROWS  512

#define GRID_MAIN 128
#define BK 64              // k per chunk (halves)
#define NCHUNK (N_SZ / BK) // 16
#define LSTR 33

#define WSTR_H 1032        // W smem row stride in halves (1024 + 8 pad, 2064B=129*16)
#define ASTR_H 72          // A smem row stride in halves (64 + 8 pad, 144B)

// ---- shared memory byte offsets ----
#define OFF_W     0                        // 32 * 1032 * 2 = 66048
#define OFF_A0    66048                    // 128 * 72 * 2  = 18432
#define OFF_A1    84480
#define OFF_SLOC  102912                   // 128*33 floats = 16896
#define OFF_XS    119808
#define OFF_KS    136704
#define OFF_FCS   153600                   // 32 floats (pad to 128)
#define OFF_BHS   153728
#define SMEM_BYTES 153856

__device__ __half g_S0[M_ROWS * N_SZ];
__device__ __half g_S1[M_ROWS * N_SZ];
__device__ float  g_X [M_ROWS * N_SZ];
__device__ float  g_F0[B_SZ * N_SZ];
__device__ float  g_fc[N_SZ];
__device__ unsigned g_bar_count = 0;
__device__ unsigned g_bar_phase = 0;

__constant__ float C_H     = 0.05f;
__constant__ float C_OMEGA = 6.283185307179586f;
__constant__ float C_GAMMA = 0.1f;
__constant__ float C_LAM   = 1.0f;
__constant__ float C_GAIN  = 0.03125f;

// ---------------------------------------------------------------------------
__global__ void init_kernel(const float* __restrict__ b_ih) {
    int idx = blockIdx.x * blockDim.x + threadIdx.x;
    int stride = gridDim.x * blockDim.x;
    for (int i = idx; i < M_ROWS * N_SZ; i += stride) g_S0[i] = __float2half(0.0f);
    if (idx < N_SZ) g_fc[idx] = tanhf(b_ih[idx]);
}

__global__ void forcing_kernel(const float* __restrict__ batch,
                               const float* __restrict__ W_ih,
                               const float* __restrict__ b_ih) {
    int idx = blockIdx.x * blockDim.x + threadIdx.x;
    int b = idx >> 10;
    int n = idx & (N_SZ - 1);
    const float4* xp = (const float4*)(batch + b * I_SZ);
    const float4* wp = (const float4*)(W_ih + n * I_SZ);
    float s = 0.0f;
#pragma unroll 8
    for (int i = 0; i < I_SZ / 4; ++i) {
        float4 x = __ldg(xp + i);
        float4 w = __ldg(wp + i);
        s += x.x * w.x + x.y * w.y + x.z * w.z + x.w * w.w;
    }
    g_F0[idx] = tanhf(s + __ldg(b_ih + n));
}

// ---------------------------------------------------------------------------
__device__ __forceinline__ void grid_barrier(unsigned G) {
    __syncthreads();
    if (threadIdx.x == 0) {
        __threadfence();                   // release whole CTA's writes
        unsigned p = *(volatile unsigned*)&g_bar_phase;
        unsigned a = atomicAdd(&g_bar_count, 1u);
        if (a == G - 1u) {
            atomicExch(&g_bar_count, 0u);
            __threadfence();
            atomicAdd(&g_bar_phase, 1u);
        } else {
            while (*(volatile unsigned*)&g_bar_phase == p) { }
        }
        __threadfence();                   // acquire
    }
    __syncthreads();
}

// ---------------------------------------------------------------------------
__device__ __forceinline__ void mma_f16(float* d, uint32_t a0, uint32_t a1,
                                        uint32_t a2, uint32_t a3,
                                        uint32_t b0, uint32_t b1) {
    asm volatile(
        "mma.sync.aligned.m16n8k16.row.col.f32.f16.f16.f32 "
        "{%0,%1,%2,%3},{%4,%5,%6,%7},{%8,%9},{%0,%1,%2,%3};"
        : "+f"(d[0]), "+f"(d[1]), "+f"(d[2]), "+f"(d[3])
        : "r"(a0), "r"(a1), "r"(a2), "r"(a3), "r"(b0), "r"(b1));
}

// ---------------------------------------------------------------------------
// main persistent kernel.
// Grid 128 = 4 m-tiles (128 rows: 64 batches x {x,y}) x 32 n-tiles (32 cols).
// W resident in SMEM (fp16). State ping-pong in GLOBAL fp16 (GEMM input only);
// fp32 state kept in per-CTA SMEM for the RK4 epilogue.
// ---------------------------------------------------------------------------
__global__ void __launch_bounds__(256, 1)
main_kernel(const float* __restrict__ W_hh, const float* __restrict__ b_hh) {
    extern __shared__ __align__(16) unsigned char smraw[];
    __half* Wsm = (__half*)(smraw + OFF_W);
    float* Sloc = (float*)(smraw + OFF_SLOC);
    float* Xs   = (float*)(smraw + OFF_XS);
    float* Ks   = (float*)(smraw + OFF_KS);
    float* fcs  = (float*)(smraw + OFF_FCS);
    float* bhs  = (float*)(smraw + OFF_BHS);

    const int tid  = threadIdx.x;
    const int lane = tid & 31;
    const int wm   = tid >> 5;            // warp 0..7 -> 16-row strip
    const int bn   = blockIdx.x & 31;
    const int bm   = blockIdx.x >> 5;
    const int N0   = bn * 32;
    const int batch0 = bm * 64;
    const unsigned G = gridDim.x;
    const bool isx = (wm < 4);

    // ---- one-time: W slice -> smem fp16 ----
    for (int i4 = tid; i4 < 32 * 256; i4 += 256) {
        int r = i4 >> 8, kpos = (i4 & 255) * 4;
        float4 w = __ldg((const float4*)(W_hh + (N0 + r) * N_SZ + kpos));
        __half2* p = (__half2*)(Wsm + r * WSTR_H + kpos);
        p[0] = __floats2half2_rn(w.x, w.y);
        p[1] = __floats2half2_rn(w.z, w.w);
    }
    for (int i = tid; i < 128 * LSTR; i += 256) { Sloc[i] = 0.0f; Xs[i] = 0.0f; Ks[i] = 0.0f; }
    if (tid < 32) { fcs[tid] = g_fc[N0 + tid]; bhs[tid] = __ldg(b_hh + N0 + tid); }
    __syncthreads();

    // ---- A loader mapping: 4 x uint4 (8 halves each) per thread per chunk ----
    const int cg = tid & 7;               // uint4 column (k offset cg*8 halves)
    int gofs[4], sofs[4];
#pragma unroll
    for (int i = 0; i < 4; ++i) {
        int arow = (tid >> 3) + 32 * i;   // tile row 0..127
        int grow = (arow < 64) ? (batch0 + arow) : (256 + batch0 + arow - 64);
        gofs[i] = grow * N_SZ + cg * 8;                 // half units
        sofs[i] = (arow * ASTR_H + cg * 8) * 2;         // bytes
    }

    __half* const bufs[2] = { g_S0, g_S1 };

    for (int t = 0; t < T_STEPS; ++t) {
        for (int s = 0; s < 4; ++s) {
            const __half* Sin = bufs[s & 1];
            __half*       Sout = bufs[(s + 1) & 1];

            float acc[4][4];
#pragma unroll
            for (int i = 0; i < 4; ++i)
#pragma unroll
                for (int j = 0; j < 4; ++j) acc[i][j] = 0.0f;

            uint4 cur[4];
#pragma unroll
            for (int i = 0; i < 4; ++i)
                cur[i] = __ldcg((const uint4*)(Sin + gofs[i]));

            for (int c = 0; c < NCHUNK; ++c) {
                unsigned char* Ab = smraw + ((c & 1) ? OFF_A1 : OFF_A0);
#pragma unroll
                for (int i = 0; i < 4; ++i)
                    *(uint4*)(Ab + sofs[i]) = cur[i];
                __syncthreads();

                if (c + 1 < NCHUNK) {
                    const int k0 = (c + 1) * BK;
#pragma unroll
                    for (int i = 0; i < 4; ++i)
                        cur[i] = __ldcg((const uint4*)(Sin + gofs[i] + k0));
                }

                const int kb = c * BK;
                const int rA = wm * 16 + (lane >> 2);
                const int qa = (lane & 3) * 2;
#pragma unroll
                for (int kk = 0; kk < BK; kk += 16) {
                    uint32_t a0 = *(const uint32_t*)(Ab + (rA * ASTR_H + kk + qa) * 2);
                    uint32_t a1 = *(const uint32_t*)(Ab + ((rA + 8) * ASTR_H + kk + qa) * 2);
                    uint32_t a2 = *(const uint32_t*)(Ab + (rA * ASTR_H + kk + qa + 8) * 2);
                    uint32_t a3 = *(const uint32_t*)(Ab + ((rA + 8) * ASTR_H + kk + qa + 8) * 2);
#pragma unroll
                    for (int nt = 0; nt < 4; ++nt) {
                        const int rB = nt * 8 + (lane >> 2);
                        uint32_t b0 = *(const uint32_t*)((const unsigned char*)Wsm
                                        + (rB * WSTR_H + kb + kk + qa) * 2);
                        uint32_t b1 = *(const uint32_t*)((const unsigned char*)Wsm
                                        + (rB * WSTR_H + kb + kk + qa + 8) * 2);
                        mma_f16(acc[nt], a0, a1, a2, a3, b0, b1);
                    }
                }
            }

            // ---------------- fused RK4-stage epilogue (SMEM-local state) -------
            const float cmul = (s == 2) ? C_H : 0.5f * C_H;
            const int r0 = wm * 16 + (lane >> 2);
            float kv[4][4];
#pragma unroll
            for (int nt = 0; nt < 4; ++nt) {
#pragma unroll
                for (int e = 0; e < 4; ++e) {
                    const int rl = r0 + 8 * (e >> 1);
                    const int cl = nt * 8 + 2 * (lane & 3) + (e & 1);
                    const int rx = isx ? rl : rl - 64;
                    const float sx = Sloc[rx * LSTR + cl];
                    const float sy = Sloc[(rx + 64) * LSTR + cl];
                    const float amp = C_LAM - (sx * sx + sy * sy);
                    const float rr = acc[nt][e];
                    float k;
                    if (isx) {
                        float F = (t == 0) ? g_F0[(batch0 + rx) * N_SZ + N0 + cl] : fcs[cl];
                        k = amp * sx - C_OMEGA * sy + C_GAIN * (rr + bhs[cl]) + F - C_GAMMA * sx;
                    } else {
                        k = amp * sy + C_OMEGA * sx + C_GAIN * (rr + bhs[cl]) - C_GAMMA * sy;
                    }
                    kv[nt][e] = k;
                }
            }
            __syncthreads();  // all Sloc reads done before overwrites
#pragma unroll
            for (int nt = 0; nt < 4; ++nt) {
#pragma unroll
                for (int eh = 0; eh < 2; ++eh) {
                    const int rl  = r0 + 8 * eh;
                    const int cl0 = nt * 8 + 2 * (lane & 3);
                    float sv[2];
#pragma unroll
                    for (int j = 0; j < 2; ++j) {
                        const int il = rl * LSTR + cl0 + j;
                        const float k = kv[nt][eh * 2 + j];
                        const float xv = Xs[il];
                        float v;
                        if (s == 0)      { Ks[il] = k;                        v = xv + cmul * k; }
                        else if (s == 3) { float xn = xv + (C_H / 6.0f) * (Ks[il] + k);
                                           Xs[il] = xn;                       v = xn; }
                        else             { Ks[il] += 2.0f * k;                v = xv + cmul * k; }
                        Sloc[il] = v;
                        sv[j] = v;
                    }
                    const int grow = batch0 + rl + (isx ? 0 : 192);
                    const int gi = grow * N_SZ + N0 + cl0;
                    *(__half2*)(Sout + gi) = __floats2half2_rn(sv[0], sv[1]);
                    if (t == T_STEPS - 1 && s == 3)
                        *(float2*)(g_X + gi) = make_float2(sv[0], sv[1]);
                }
            }
            grid_barrier(G);
        }
    }
}

// ---------------------------------------------------------------------------
__global__ void out_kernel(const float* __restrict__ W_ho,
                           const float* __restrict__ b_ho,
                           float* __restrict__ out) {
    int b   = blockIdx.x;
    int tid = threadIdx.x;
    int o   = tid >> 2;
    int q   = tid & 3;
    const float4* xp = (const float4*)(g_X + b * N_SZ + q * 256);
    const float4* wp = (const float4*)(W_ho + o * N_SZ + q * 256);
    float s = 0.0f;
#pragma unroll 8
    for (int i = 0; i < 64; ++i) {
        float4 x = xp[i];
        float4 w = __ldg(wp + i);
        s += x.x * w.x + x.y * w.y + x.z * w.z + x.w * w.w;
    }
    s += __shfl_xor_sync(0xffffffffu, s, 1);
    s += __shfl_xor_sync(0xffffffffu, s, 2);
    if (q == 0) out[b * O_SZ + o] = s + __ldg(b_ho + o);
}

// ---------------------------------------------------------------------------
extern "C" void kernel_launch(void* const* d_in, const int* in_sizes, int n_in,
                              void* d_out, int out_size) {
    const float* batch = (const float*)d_in[0];
    const float* W_ih  = (const float*)d_in[1];
    const float* b_ih  = (const float*)d_in[2];
    const float* W_hh  = (const float*)d_in[3];
    const float* b_hh  = (const float*)d_in[4];
    const float* W_ho  = (const float*)d_in[5];
    const float* b_ho  = (const float*)d_in[6];
    float* out = (float*)d_out;

    cudaFuncSetAttribute(main_kernel,
                         cudaFuncAttributeMaxDynamicSharedMemorySize, SMEM_BYTES);

    init_kernel<<<512, 256>>>(b_ih);
    forcing_kernel<<<(B_SZ * N_SZ) / 256, 256>>>(batch, W_ih, b_ih);
    main_kernel<<<GRID_MAIN, 256, SMEM_BYTES>>>(W_hh, b_hh);
    out_kernel<<<B_SZ, 256>>>(W_ho, b_ho, out);
}

// round 6
// speedup vs baseline: 2.3996x; 1.2393x over previous
#include <cuda_runtime.h>
#include <cuda_fp16.h>
#include <math.h>
#include <stdint.h>

#define T_STEPS 256
#define B_SZ    256
#define I_SZ    128
#define N_SZ    1024
#define O_SZ    64
#define M_ROWS  512

#define GRID_MAIN 128
#define BK 64              // k per chunk (halves)
#define NCHUNK (N_SZ / BK) // 16
#define LSTR 33

#define WSTR_H 1032        // W smem row stride (halves); 2064B = bank+4 per row
#define ASTR_H 72          // A smem row stride (halves); 144B  = bank+4 per row
#define ABUF_B 18432       // one A buffer: 128 * 72 * 2

// ---- shared memory byte offsets ----
#define OFF_W     0                        // 32*1032*2 = 66048
#define OFF_A     66048                    // 3 buffers x 18432 = 55296
#define OFF_SLOC  121344                   // 128*33 floats = 16896
#define OFF_XS    138240
#define OFF_KS    155136
#define OFF_FCS   172032                   // 32 floats (pad 128)
#define OFF_BHS   172160
#define SMEM_BYTES 172288

__device__ __half g_S0[M_ROWS * N_SZ];
__device__ __half g_S1[M_ROWS * N_SZ];
__device__ float  g_X [M_ROWS * N_SZ];
__device__ float  g_F0[B_SZ * N_SZ];
__device__ float  g_fc[N_SZ];
__device__ unsigned g_bar_count[4 * 32];   // one counter per 32-CTA group, 128B apart
__device__ unsigned g_bar_phase[4 * 32];

__constant__ float C_H     = 0.05f;
__constant__ float C_OMEGA = 6.283185307179586f;
__constant__ float C_GAMMA = 0.1f;
__constant__ float C_LAM   = 1.0f;
__constant__ float C_GAIN  = 0.03125f;

// ---------------------------------------------------------------------------
__global__ void init_kernel(const float* __restrict__ b_ih) {
    int idx = blockIdx.x * blockDim.x + threadIdx.x;
    int stride = gridDim.x * blockDim.x;
    for (int i = idx; i < M_ROWS * N_SZ; i += stride) g_S0[i] = __float2half(0.0f);
    if (idx < N_SZ) g_fc[idx] = tanhf(b_ih[idx]);
}

__global__ void forcing_kernel(const float* __restrict__ batch,
                               const float* __restrict__ W_ih,
                               const float* __restrict__ b_ih) {
    int idx = blockIdx.x * blockDim.x + threadIdx.x;
    int b = idx >> 10;
    int n = idx & (N_SZ - 1);
    const float4* xp = (const float4*)(batch + b * I_SZ);
    const float4* wp = (const float4*)(W_ih + n * I_SZ);
    float s = 0.0f;
#pragma unroll 8
    for (int i = 0; i < I_SZ / 4; ++i) {
        float4 x = __ldg(xp + i);
        float4 w = __ldg(wp + i);
        s += x.x * w.x + x.y * w.y + x.z * w.z + x.w * w.w;
    }
    g_F0[idx] = tanhf(s + __ldg(b_ih + n));
}

// ---------------------------------------------------------------------------
// group-local barrier: only the 32 CTAs of one bm-group synchronize.
// ---------------------------------------------------------------------------
__device__ __forceinline__ void group_barrier(int grp) {
    __syncthreads();
    if (threadIdx.x == 0) {
        __threadfence();                   // release whole CTA's writes
        volatile unsigned* ph = &g_bar_phase[grp * 32];
        unsigned p = *ph;
        unsigned a = atomicAdd(&g_bar_count[grp * 32], 1u);
        if (a == 31u) {
            atomicExch(&g_bar_count[grp * 32], 0u);
            __threadfence();
            atomicAdd(&g_bar_phase[grp * 32], 1u);
        } else {
            while (*ph == p) { }
        }
        __threadfence();                   // acquire
    }
    __syncthreads();
}

// ---------------------------------------------------------------------------
__device__ __forceinline__ void mma_f16(float* d, uint32_t a0, uint32_t a1,
                                        uint32_t a2, uint32_t a3,
                                        uint32_t b0, uint32_t b1) {
    asm volatile(
        "mma.sync.aligned.m16n8k16.row.col.f32.f16.f16.f32 "
        "{%0,%1,%2,%3},{%4,%5,%6,%7},{%8,%9},{%0,%1,%2,%3};"
        : "+f"(d[0]), "+f"(d[1]), "+f"(d[2]), "+f"(d[3])
        : "r"(a0), "r"(a1), "r"(a2), "r"(a3), "r"(b0), "r"(b1));
}

__device__ __forceinline__ void ldsm4(uint32_t& r0, uint32_t& r1, uint32_t& r2,
                                      uint32_t& r3, uint32_t addr) {
    asm volatile("ldmatrix.sync.aligned.m8n8.x4.shared.b16 {%0,%1,%2,%3}, [%4];"
                 : "=r"(r0), "=r"(r1), "=r"(r2), "=r"(r3) : "r"(addr));
}

__device__ __forceinline__ void cp16(uint32_t s, const void* g) {
    asm volatile("cp.async.cg.shared.global [%0], [%1], 16;"
                 :: "r"(s), "l"(g) : "memory");
}
__device__ __forceinline__ void cp_commit() {
    asm volatile("cp.async.commit_group;" ::: "memory");
}

__device__ __forceinline__ uint32_t smem_u32(const void* p) {
    uint32_t a;
    asm("{ .reg .u64 t; cvta.to.shared.u64 t, %1; cvt.u32.u64 %0, t; }" : "=r"(a) : "l"(p));
    return a;
}

// ---------------------------------------------------------------------------
// main persistent kernel.
// Grid 128 = 4 independent 32-CTA groups (one per 64-batch m-tile).
// W resident in SMEM (fp16). A: cp.async 3-deep pipeline. ldmatrix frags.
// ---------------------------------------------------------------------------
__global__ void __launch_bounds__(256, 1)
main_kernel(const float* __restrict__ W_hh, const float* __restrict__ b_hh) {
    extern __shared__ __align__(16) unsigned char smraw[];
    __half* Wsm = (__half*)(smraw + OFF_W);
    float* Sloc = (float*)(smraw + OFF_SLOC);
    float* Xs   = (float*)(smraw + OFF_XS);
    float* Ks   = (float*)(smraw + OFF_KS);
    float* fcs  = (float*)(smraw + OFF_FCS);
    float* bhs  = (float*)(smraw + OFF_BHS);

    const int tid  = threadIdx.x;
    const int lane = tid & 31;
    const int wm   = tid >> 5;            // warp 0..7 -> 16-row strip
    const int bn   = blockIdx.x & 31;
    const int bm   = blockIdx.x >> 5;
    const int N0   = bn * 32;
    const int batch0 = bm * 64;
    const bool isx = (wm < 4);

    const uint32_t sbase = smem_u32(smraw);
    const uint32_t abase = sbase + OFF_A;

    // ---- one-time: W slice -> smem fp16 ----
    for (int i4 = tid; i4 < 32 * 256; i4 += 256) {
        int r = i4 >> 8, kpos = (i4 & 255) * 4;
        float4 w = __ldg((const float4*)(W_hh + (N0 + r) * N_SZ + kpos));
        __half2* p = (__half2*)(Wsm + r * WSTR_H + kpos);
        p[0] = __floats2half2_rn(w.x, w.y);
        p[1] = __floats2half2_rn(w.z, w.w);
    }
    for (int i = tid; i < 128 * LSTR; i += 256) { Sloc[i] = 0.0f; Xs[i] = 0.0f; Ks[i] = 0.0f; }
    if (tid < 32) { fcs[tid] = g_fc[N0 + tid]; bhs[tid] = __ldg(b_hh + N0 + tid); }
    __syncthreads();

    // ---- cp.async loader mapping: 4 x 16B per thread per chunk ----
    int gofs[4];        // half units into Sin
    uint32_t sofs[4];   // bytes into A buffer
    {
        const int cg = tid & 7;
#pragma unroll
        for (int i = 0; i < 4; ++i) {
            int arow = (tid >> 3) + 32 * i;
            int grow = (arow < 64) ? (batch0 + arow) : (256 + batch0 + arow - 64);
            gofs[i] = grow * N_SZ + cg * 8;
            sofs[i] = (uint32_t)(arow * ASTR_H + cg * 8) * 2;
        }
    }

    // ---- ldmatrix lane addresses ----
    // A: lane -> row = wm*16 + (l%8) + ((l&8)?8:0), kadd = (l&16)?8:0
    const uint32_t aoff_l =
        (uint32_t)(((wm * 16 + (lane & 7) + ((lane & 8) ? 8 : 0)) * ASTR_H
                    + ((lane & 16) ? 8 : 0)) * 2);
    // W pair p: row = p*16 + (l%8) + ((l&16)?8:0), kadd = (l&8)?8:0
    uint32_t woff[2];
#pragma unroll
    for (int p = 0; p < 2; ++p)
        woff[p] = sbase + OFF_W +
            (uint32_t)(((p * 16 + (lane & 7) + ((lane & 16) ? 8 : 0)) * WSTR_H
                        + ((lane & 8) ? 8 : 0)) * 2);

    __half* const bufs[2] = { g_S0, g_S1 };

    for (int t = 0; t < T_STEPS; ++t) {
        for (int s = 0; s < 4; ++s) {
            const __half* Sin = bufs[s & 1];
            __half*       Sout = bufs[(s + 1) & 1];

            float acc[4][4];
#pragma unroll
            for (int i = 0; i < 4; ++i)
#pragma unroll
                for (int j = 0; j < 4; ++j) acc[i][j] = 0.0f;

            // prologue: stages 0,1
#pragma unroll
            for (int st = 0; st < 2; ++st) {
                const uint32_t ab = abase + st * ABUF_B;
#pragma unroll
                for (int i = 0; i < 4; ++i)
                    cp16(ab + sofs[i], Sin + gofs[i] + st * BK);
                cp_commit();
            }

            for (int c = 0; c < NCHUNK; ++c) {
                if (c == NCHUNK - 1)
                    asm volatile("cp.async.wait_group 0;" ::: "memory");
                else
                    asm volatile("cp.async.wait_group 1;" ::: "memory");
                __syncthreads();

                if (c + 2 < NCHUNK) {
                    const int st = c + 2;
                    const uint32_t ab = abase + (st % 3) * ABUF_B;
#pragma unroll
                    for (int i = 0; i < 4; ++i)
                        cp16(ab + sofs[i], Sin + gofs[i] + st * BK);
                    cp_commit();
                }

                const uint32_t ab = abase + (c % 3) * ABUF_B;
                const uint32_t wk = (uint32_t)(c * BK * 2);
#pragma unroll
                for (int kk = 0; kk < BK; kk += 16) {
                    uint32_t a0, a1, a2, a3;
                    ldsm4(a0, a1, a2, a3, ab + aoff_l + kk * 2);
                    uint32_t b00, b01, b10, b11;
                    ldsm4(b00, b01, b10, b11, woff[0] + wk + kk * 2);
                    uint32_t b20, b21, b30, b31;
                    ldsm4(b20, b21, b30, b31, woff[1] + wk + kk * 2);
                    mma_f16(acc[0], a0, a1, a2, a3, b00, b01);
                    mma_f16(acc[1], a0, a1, a2, a3, b10, b11);
                    mma_f16(acc[2], a0, a1, a2, a3, b20, b21);
                    mma_f16(acc[3], a0, a1, a2, a3, b30, b31);
                }
            }

            // ---------------- fused RK4-stage epilogue (SMEM-local state) -------
            const float cmul = (s == 2) ? C_H : 0.5f * C_H;
            const int r0 = wm * 16 + (lane >> 2);
            float kv[4][4];
#pragma unroll
            for (int nt = 0; nt < 4; ++nt) {
#pragma unroll
                for (int e = 0; e < 4; ++e) {
                    const int rl = r0 + 8 * (e >> 1);
                    const int cl = nt * 8 + 2 * (lane & 3) + (e & 1);
                    const int rx = isx ? rl : rl - 64;
                    const float sx = Sloc[rx * LSTR + cl];
                    const float sy = Sloc[(rx + 64) * LSTR + cl];
                    const float amp = C_LAM - (sx * sx + sy * sy);
                    const float rr = acc[nt][e];
                    float k;
                    if (isx) {
                        float F = (t == 0) ? g_F0[(batch0 + rx) * N_SZ + N0 + cl] : fcs[cl];
                        k = amp * sx - C_OMEGA * sy + C_GAIN * (rr + bhs[cl]) + F - C_GAMMA * sx;
                    } else {
                        k = amp * sy + C_OMEGA * sx + C_GAIN * (rr + bhs[cl]) - C_GAMMA * sy;
                    }
                    kv[nt][e] = k;
                }
            }
            __syncthreads();  // all Sloc reads done before overwrites
#pragma unroll
            for (int nt = 0; nt < 4; ++nt) {
#pragma unroll
                for (int eh = 0; eh < 2; ++eh) {
                    const int rl  = r0 + 8 * eh;
                    const int cl0 = nt * 8 + 2 * (lane & 3);
                    float sv[2];
#pragma unroll
                    for (int j = 0; j < 2; ++j) {
                        const int il = rl * LSTR + cl0 + j;
                        const float k = kv[nt][eh * 2 + j];
                        const float xv = Xs[il];
                        float v;
                        if (s == 0)      { Ks[il] = k;                        v = xv + cmul * k; }
                        else if (s == 3) { float xn = xv + (C_H / 6.0f) * (Ks[il] + k);
                                           Xs[il] = xn;                       v = xn; }
                        else             { Ks[il] += 2.0f * k;                v = xv + cmul * k; }
                        Sloc[il] = v;
                        sv[j] = v;
                    }
                    const int grow = batch0 + rl + (isx ? 0 : 192);
                    const int gi = grow * N_SZ + N0 + cl0;
                    *(__half2*)(Sout + gi) = __floats2half2_rn(sv[0], sv[1]);
                    if (t == T_STEPS - 1 && s == 3)
                        *(float2*)(g_X + gi) = make_float2(sv[0], sv[1]);
                }
            }
            group_barrier(bm);
        }
    }
}

// ---------------------------------------------------------------------------
__global__ void out_kernel(const float* __restrict__ W_ho,
                           const float* __restrict__ b_ho,
                           float* __restrict__ out) {
    int b   = blockIdx.x;
    int tid = threadIdx.x;
    int o   = tid >> 2;
    int q   = tid & 3;
    const float4* xp = (const float4*)(g_X + b * N_SZ + q * 256);
    const float4* wp = (const float4*)(W_ho + o * N_SZ + q * 256);
    float s = 0.0f;
#pragma unroll 8
    for (int i = 0; i < 64; ++i) {
        float4 x = xp[i];
        float4 w = __ldg(wp + i);
        s += x.x * w.x + x.y * w.y + x.z * w.z + x.w * w.w;
    }
    s += __shfl_xor_sync(0xffffffffu, s, 1);
    s += __shfl_xor_sync(0xffffffffu, s, 2);
    if (q == 0) out[b * O_SZ + o] = s + __ldg(b_ho + o);
}

// ---------------------------------------------------------------------------
extern "C" void kernel_launch(void* const* d_in, const int* in_sizes, int n_in,
                              void* d_out, int out_size) {
    const float* batch = (const float*)d_in[0];
    const float* W_ih  = (const float*)d_in[1];
    const float* b_ih  = (const float*)d_in[2];
    const float* W_hh  = (const float*)d_in[3];
    const float* b_hh  = (const float*)d_in[4];
    const float* W_ho  = (const float*)d_in[5];
    const float* b_ho  = (const float*)d_in[6];
    float* out = (float*)d_out;

    cudaFuncSetAttribute(main_kernel,
                         cudaFuncAttributeMaxDynamicSharedMemorySize, SMEM_BYTES);

    init_kernel<<<512, 256>>>(b_ih);
    forcing_kernel<<<(B_SZ * N_SZ) / 256, 256>>>(batch, W_ih, b_ih);
    main_kernel<<<GRID_MAIN, 256, SMEM_BYTES>>>(W_hh, b_hh);
    out_kernel<<<B_SZ, 256>>>(W_ho, b_ho, out);
}